// round 1
// baseline (speedup 1.0000x reference)
#include <cuda_runtime.h>
#include <math.h>

// Problem constants
#define B_   4
#define H_   256
#define W_   256
#define CI   64
#define CM   512
#define NA   9

// Tiling
#define TH   8          // tile height (rows)
#define TW   16         // tile width  (cols)
#define CB   16         // mid-channel block
#define WSTR 580        // padded per-channel weight stride (floats), %4==0 for float4, odd/32-friendly

// Dynamic smem layout (floats):
//   xs4  : 16 ci4-groups x 10 rows x 18 cols  (float4)  = 2880 float4 = 11520 floats
//   ws   : CB x WSTR                                    =  9280 floats
//   wcat : CB x 48                                      =   768 floats
//   feats: CB x 128                                     =  2048 floats
// total = 23616 floats = 94464 bytes  -> 2 blocks/SM
#define SMEM_FLOATS 23616
#define SMEM_BYTES  (SMEM_FLOATS * 4)

__global__ __launch_bounds__(128, 2)
void rpn_fused_kernel(const float* __restrict__ x,
                      const float* __restrict__ w_base,
                      const float* __restrict__ b_base,
                      const float* __restrict__ w_cls,
                      const float* __restrict__ b_cls,
                      const float* __restrict__ w_reg,
                      const float* __restrict__ b_reg,
                      float* __restrict__ out)
{
    extern __shared__ float smem[];
    float4* xs4   = (float4*)smem;                    // [ci4][y][x] : [16][10][18]
    float*  ws    = smem + 11520;                     // [CB][WSTR]
    float*  wcat  = ws + CB * WSTR;                   // [CB][48] (0..8 cls, 9..44 reg, pad)
    float*  feats = wcat + CB * 48;                   // [CB][128]

    const int tid = threadIdx.x;
    const int bid = blockIdx.x;
    const int b   = bid >> 9;          // 512 tiles per image (32 y-tiles * 16 x-tiles)
    const int tno = bid & 511;
    const int ty  = tno >> 4;          // 0..31
    const int tx  = tno & 15;          // 0..15
    const int gy0 = ty * TH;
    const int gx0 = tx * TW;

    // ---- Load x window [10][18][64] into xs4[ci4][y][x] (zero-padded SAME borders) ----
    const float* xb = x + (long)b * H_ * W_ * CI;
    for (int e = tid; e < 16 * 10 * 18; e += 128) {
        int ci4 = e & 15;
        int rem = e >> 4;
        int xx  = rem % 18;
        int yy  = rem / 18;
        int gy  = gy0 + yy - 1;
        int gx  = gx0 + xx - 1;
        float4 v = make_float4(0.f, 0.f, 0.f, 0.f);
        if ((unsigned)gy < (unsigned)H_ && (unsigned)gx < (unsigned)W_) {
            v = *(const float4*)(xb + ((long)gy * W_ + gx) * CI + ci4 * 4);
        }
        xs4[ci4 * 180 + yy * 18 + xx] = v;
    }

    // Thread roles
    const int cg = tid >> 5;   // warp id -> channel group (4 channels), warp-uniform
    const int pg = tid & 31;   // position group: positions pg, pg+32, pg+64, pg+96
    const int x0 = pg & 15;
    const int y0 = pg >> 4;

    // Persistent per-position output accumulators (48, 45 used) — constant-indexed, stays in regs
    float acc[48];
    #pragma unroll
    for (int j = 0; j < 48; j++) acc[j] = 0.f;

    for (int cb = 0; cb < CM; cb += CB) {
        __syncthreads();   // protect ws/wcat from previous stage B readers (and xs on iter 0)

        // ---- Cooperative load: transposed base weights ws[ch][k], k in [0,576) ----
        for (int e = tid; e < CB * 576; e += 128) {
            int ch = e & 15;
            int k  = e >> 4;
            ws[ch * WSTR + k] = w_base[(long)k * CM + cb + ch];
        }
        // ---- 1x1 head weights: wcat[ch][0..8]=cls, [9..44]=reg, pad zeros ----
        for (int e = tid; e < CB * 48; e += 128) {
            int ch = e / 48;
            int j  = e % 48;
            int c  = cb + ch;
            float v = 0.f;
            if (j < 9)       v = w_cls[c * NA + j];
            else if (j < 45) v = w_reg[c * 36 + (j - 9)];
            wcat[ch * 48 + j] = v;
        }
        __syncthreads();

        // ---- Stage A: 4 positions x 4 channels register microkernel over K=576 ----
        float facc[4][4];
        #pragma unroll
        for (int c = 0; c < 4; c++)
            #pragma unroll
            for (int p = 0; p < 4; p++) facc[c][p] = 0.f;

        #pragma unroll 1
        for (int ky = 0; ky < 3; ky++) {
            #pragma unroll 1
            for (int kx = 0; kx < 3; kx++) {
                const float4* xrow = xs4 + (y0 + ky) * 18 + (x0 + kx);
                const float*  wk   = ws + cg * 4 * WSTR + (ky * 3 + kx) * 64;
                #pragma unroll 4
                for (int ci4 = 0; ci4 < 16; ci4++) {
                    float4 xv[4];
                    #pragma unroll
                    for (int p = 0; p < 4; p++)
                        xv[p] = xrow[ci4 * 180 + p * 36];   // rows y0, y0+2, y0+4, y0+6
                    #pragma unroll
                    for (int c = 0; c < 4; c++) {
                        float4 wv = *(const float4*)(wk + c * WSTR + ci4 * 4); // warp-broadcast
                        #pragma unroll
                        for (int p = 0; p < 4; p++) {
                            facc[c][p] = fmaf(xv[p].x, wv.x, facc[c][p]);
                            facc[c][p] = fmaf(xv[p].y, wv.y, facc[c][p]);
                            facc[c][p] = fmaf(xv[p].z, wv.z, facc[c][p]);
                            facc[c][p] = fmaf(xv[p].w, wv.w, facc[c][p]);
                        }
                    }
                }
            }
        }

        // bias + relu -> feats[ch][pos]
        #pragma unroll
        for (int c = 0; c < 4; c++) {
            float bb = __ldg(&b_base[cb + cg * 4 + c]);
            #pragma unroll
            for (int p = 0; p < 4; p++) {
                float f = facc[c][p] + bb;
                feats[(cg * 4 + c) * 128 + pg + 32 * p] = fmaxf(f, 0.f);
            }
        }
        __syncthreads();

        // ---- Stage B: each thread owns position `tid`, accumulates 45 outputs ----
        #pragma unroll 4
        for (int ch = 0; ch < CB; ch++) {
            float f = feats[ch * 128 + tid];
            const float4* wc = (const float4*)(wcat + ch * 48);
            #pragma unroll
            for (int j = 0; j < 12; j++) {
                float4 wv = wc[j];                       // warp-broadcast
                acc[4 * j + 0] = fmaf(f, wv.x, acc[4 * j + 0]);
                acc[4 * j + 1] = fmaf(f, wv.y, acc[4 * j + 1]);
                acc[4 * j + 2] = fmaf(f, wv.z, acc[4 * j + 2]);
                acc[4 * j + 3] = fmaf(f, wv.w, acc[4 * j + 3]);
            }
        }
    }

    // ---- Epilogue: sigmoid scores, threshold-masked deltas ----
    const int ly = tid >> 4;
    const int lx = tid & 15;
    const int gy = gy0 + ly;
    const int gx = gx0 + lx;
    float* o = out + (((long)b * H_ + gy) * W_ + gx) * 45;

    float sc[9];
    #pragma unroll
    for (int j = 0; j < 9; j++) {
        float z = acc[j] + __ldg(&b_cls[j]);
        sc[j] = 1.f / (1.f + __expf(-z));
        o[j] = sc[j];
    }
    #pragma unroll
    for (int an = 0; an < 9; an++) {
        float m = sc[an] > 0.7f ? 1.f : 0.f;
        #pragma unroll
        for (int i = 0; i < 4; i++) {
            int j = 9 + an * 4 + i;
            o[j] = (acc[j] + __ldg(&b_reg[an * 4 + i])) * m;
        }
    }
}

extern "C" void kernel_launch(void* const* d_in, const int* in_sizes, int n_in,
                              void* d_out, int out_size)
{
    const float* x      = (const float*)d_in[0];
    const float* w_base = (const float*)d_in[1];
    const float* b_base = (const float*)d_in[2];
    const float* w_cls  = (const float*)d_in[3];
    const float* b_cls  = (const float*)d_in[4];
    const float* w_reg  = (const float*)d_in[5];
    const float* b_reg  = (const float*)d_in[6];
    float* out = (float*)d_out;

    // Not a stream op — safe under graph capture; idempotent every call.
    cudaFuncSetAttribute(rpn_fused_kernel,
                         cudaFuncAttributeMaxDynamicSharedMemorySize, SMEM_BYTES);

    // 4 images * 32 y-tiles * 16 x-tiles = 2048 blocks
    rpn_fused_kernel<<<2048, 128, SMEM_BYTES>>>(
        x, w_base, b_base, w_cls, b_cls, w_reg, b_reg, out);
}